// round 10
// baseline (speedup 1.0000x reference)
#include <cuda_runtime.h>
#include <cstdint>

#define NB 128
#define TILE 128
#define FS 132
#define N_ATOMS_MAX 50000

typedef unsigned long long ull;

// Scratch (device globals: allocation-free per harness rules)
__device__ float g_h[N_ATOMS_MAX * NB];
__device__ float g_agg[N_ATOMS_MAX * NB];
__device__ float g_t[N_ATOMS_MAX * NB];

// ---------------- helpers ----------------

__device__ __forceinline__ float sspf(float x) {
    float e = __expf(-fabsf(x));
    return fmaxf(x, 0.0f) + __logf(1.0f + e) - 0.69314718055994531f;
}
__device__ __forceinline__ ull pack2(float x, float y) {
    ull r; asm("mov.b64 %0, {%1, %2};" : "=l"(r) : "f"(x), "f"(y)); return r;
}
__device__ __forceinline__ ull dupf(float w) {
    ull r; asm("mov.b64 %0, {%1, %1};" : "=l"(r) : "f"(w)); return r;
}
__device__ __forceinline__ void unpack2(ull v, float& x, float& y) {
    asm("mov.b64 {%0, %1}, %2;" : "=f"(x), "=f"(y) : "l"(v));
}
__device__ __forceinline__ void fma2(ull& d, ull a, ull b) {
    asm("fma.rn.f32x2 %0, %1, %2, %3;" : "=l"(d) : "l"(a), "l"(b), "l"(d));
}
__device__ __forceinline__ void red4(float* p, float a, float b, float c, float d) {
    asm volatile("red.global.add.v4.f32 [%0], {%1,%2,%3,%4};"
                 :: "l"(p), "f"(a), "f"(b), "f"(c), "f"(d) : "memory");
}

// ---------------- zero / dummy ----------------
__global__ void zero_kernel(float4* __restrict__ p, int n4) {
    int i = blockIdx.x * blockDim.x + threadIdx.x;
    if (i < n4) p[i] = make_float4(0.f, 0.f, 0.f, 0.f);
}
__global__ void dummy_kernel() {}

// ---------------- row GEMM: Y = [ssp](X @ W + b), K=N=128, 8 rows/iter ----
template <bool DOSSP>
__global__ __launch_bounds__(128, 2) void rowmm_kernel(
    const float* __restrict__ X, const float* __restrict__ W,
    const float* __restrict__ b, float* __restrict__ Y, int nrows) {
    const int j = threadIdx.x;
    float wr[NB];
#pragma unroll
    for (int k = 0; k < NB; k++) wr[k] = W[k * NB + j];
    const float bj = b[j];
    __shared__ __align__(16) float xsh[NB * 8];
    const int ngroups = (nrows + 7) / 8;
    for (int g = blockIdx.x; g < ngroups; g += gridDim.x) {
        const int row0 = g * 8;
        __syncthreads();
#pragma unroll
        for (int r = 0; r < 8; r++) {
            int row = row0 + r;
            xsh[j * 8 + r] = (row < nrows) ? X[row * NB + j] : 0.0f;
        }
        __syncthreads();
        ull a0 = pack2(bj, bj), a1 = a0, a2 = a0, a3 = a0;
        const ulonglong2* xs2 = (const ulonglong2*)xsh;
#pragma unroll
        for (int k = 0; k < NB; k++) {
            ulonglong2 fa = xs2[2 * k];
            ulonglong2 fb = xs2[2 * k + 1];
            ull wd = dupf(wr[k]);
            fma2(a0, fa.x, wd); fma2(a1, fa.y, wd);
            fma2(a2, fb.x, wd); fma2(a3, fb.y, wd);
        }
        float yv[8];
        unpack2(a0, yv[0], yv[1]); unpack2(a1, yv[2], yv[3]);
        unpack2(a2, yv[4], yv[5]); unpack2(a3, yv[6], yv[7]);
        if (DOSSP) {
#pragma unroll
            for (int r = 0; r < 8; r++) yv[r] = sspf(yv[r]);
        }
#pragma unroll
        for (int r = 0; r < 8; r++) {
            int row = row0 + r;
            if (row < nrows) Y[row * NB + j] = yv[r];
        }
    }
}

// ---------------- pair kernel: 128-pair tile, 8x8 thread tile ----------------
// smem float offsets
#define SM_W2  0                      // 128*128 = 16384
#define SM_F   16384                  // 20*FS   = 2640
#define SM_U   19024                  // 128*FS  = 16896 (aliased by ws [p][j])
#define SM_II  35920
#define SM_IJ  36048
#define SM_RC  36176
#define SM_FLOATS 36304
#define SM_BYTES (SM_FLOATS * 4)

__global__ __launch_bounds__(256) void pair_kernel(
    const float* __restrict__ f_ij, const float* __restrict__ rcut,
    const float* __restrict__ Wf1, const float* __restrict__ bf1,
    const float* __restrict__ Wf2, const float* __restrict__ bf2,
    const int* __restrict__ idx_i, const int* __restrict__ idx_j,
    const float* __restrict__ h, float* __restrict__ agg, int npairs) {
    extern __shared__ __align__(16) float sm[];
    float* W2s = sm + SM_W2;
    float* fs  = sm + SM_F;
    float* us  = sm + SM_U;
    float* ws  = sm + SM_U;            // union: written after all u reads
    int*   iis = (int*)(sm + SM_II);
    int*   ijs = (int*)(sm + SM_IJ);
    float* rcs = sm + SM_RC;

    const int tid  = threadIdx.x;
    const int wid  = tid >> 5;
    const int lane = tid & 31;

    // persistent: Wf2 -> smem
    for (int i = tid * 4; i < NB * NB; i += 1024)
        *(float4*)(W2s + i) = *(const float4*)(Wf2 + i);

    // stage-1 ownership: column j1, pair half
    const int j1   = tid & 127;
    const int half = tid >> 7;
    float w1r[20];
#pragma unroll
    for (int k = 0; k < 20; k++) w1r[k] = Wf1[k * NB + j1];
    const float b1 = bf1[j1];

    // stage-2 thread tile: 8 pairs x 8 cols
    const int pairg = (wid << 1) | (lane >> 4);    // 0..15
    const int pr0   = pairg << 3;
    const int colg  = lane & 15;                   // 0..15
    const int c0    = colg << 3;
    float b2v[8];
    {
        float4 ba = *(const float4*)(bf2 + c0);
        float4 bb = *(const float4*)(bf2 + c0 + 4);
        b2v[0] = ba.x; b2v[1] = ba.y; b2v[2] = ba.z; b2v[3] = ba.w;
        b2v[4] = bb.x; b2v[5] = bb.y; b2v[6] = bb.z; b2v[7] = bb.w;
    }

    const int ntiles = (npairs + TILE - 1) / TILE;
    for (int t = blockIdx.x; t < ntiles; t += gridDim.x) {
        const int base = t * TILE;
        __syncthreads();  // prev tile's ws reads done; W2 load done (first iter)

        // --- f tile load + transpose to fs[k][p] ---
        if (base + TILE <= npairs) {
            for (int vi = tid; vi < TILE * 5; vi += 256) {
                float4 v = ((const float4*)f_ij)[base * 5 + vi];
                int g = vi * 4;
                int p = g / 20, k = g - p * 20;   // k in {0,4,8,12,16}
                fs[(k + 0) * FS + p] = v.x;
                fs[(k + 1) * FS + p] = v.y;
                fs[(k + 2) * FS + p] = v.z;
                fs[(k + 3) * FS + p] = v.w;
            }
        } else {
            for (int vi = tid; vi < TILE * 20; vi += 256) {
                int p = vi / 20, k = vi - p * 20;
                int e = base + p;
                fs[k * FS + p] = (e < npairs) ? f_ij[e * 20 + k] : 0.0f;
            }
        }
        if (tid < TILE) {
            int e = base + tid;
            bool v = (e < npairs);
            iis[tid] = v ? idx_i[e] : 0;
            ijs[tid] = v ? idx_j[e] : 0;
            rcs[tid] = v ? rcut[e] : 0.0f;
        }
        __syncthreads();

        // --- stage 1: u[p][j1] for 64 pairs (this half) ---
        {
            ull a[32];
            ull bi = pack2(b1, b1);
#pragma unroll
            for (int i = 0; i < 32; i++) a[i] = bi;
            const float* fb = fs + half * 64;
#pragma unroll
            for (int k = 0; k < 20; k++) {
                const ulonglong2* fp = (const ulonglong2*)(fb + k * FS);
                ull wd = dupf(w1r[k]);
#pragma unroll
                for (int q = 0; q < 16; q++) {
                    ulonglong2 fv = fp[q];
                    fma2(a[2 * q], fv.x, wd);
                    fma2(a[2 * q + 1], fv.y, wd);
                }
            }
            float v[64];
#pragma unroll
            for (int i = 0; i < 32; i++) unpack2(a[i], v[2 * i], v[2 * i + 1]);
#pragma unroll
            for (int i = 0; i < 64; i++) v[i] = sspf(v[i]);
            float* ub = us + j1 * FS + half * 64;
#pragma unroll
            for (int q = 0; q < 16; q++)
                *(float4*)(ub + q * 4) =
                    make_float4(v[4 * q], v[4 * q + 1], v[4 * q + 2], v[4 * q + 3]);
        }
        __syncthreads();

        // --- stage 2: acc[8 cols][4 pair-pairs] over k=0..127 ---
        ull acc[32];
#pragma unroll
        for (int c = 0; c < 8; c++) {
            ull bd = dupf(b2v[c]);
            acc[c * 4 + 0] = bd; acc[c * 4 + 1] = bd;
            acc[c * 4 + 2] = bd; acc[c * 4 + 3] = bd;
        }
        {
            const float* up = us + pr0;
            const float* wp = W2s + c0;
#pragma unroll 4
            for (int k = 0; k < NB; k++) {
                ulonglong2 ua = *(const ulonglong2*)(up + k * FS);
                ulonglong2 ub = *(const ulonglong2*)(up + k * FS + 4);
                float4 wva = *(const float4*)(wp + k * NB);
                float4 wvb = *(const float4*)(wp + k * NB + 4);
                float wf[8] = {wva.x, wva.y, wva.z, wva.w,
                               wvb.x, wvb.y, wvb.z, wvb.w};
#pragma unroll
                for (int c = 0; c < 8; c++) {
                    ull wd = dupf(wf[c]);
                    fma2(acc[c * 4 + 0], ua.x, wd);
                    fma2(acc[c * 4 + 1], ua.y, wd);
                    fma2(acc[c * 4 + 2], ub.x, wd);
                    fma2(acc[c * 4 + 3], ub.y, wd);
                }
            }
        }
        __syncthreads();  // all u reads done; ws aliases us

        // --- transpose (+rcut) into ws[p][j] ---
#pragma unroll
        for (int pp = 0; pp < 4; pp++) {
            int p_lo = pr0 + 2 * pp, p_hi = p_lo + 1;
            float rl = rcs[p_lo], rh = rcs[p_hi];
            float lo[8], hi[8];
#pragma unroll
            for (int c = 0; c < 8; c++) unpack2(acc[c * 4 + pp], lo[c], hi[c]);
            *(float4*)(ws + p_lo * FS + c0) =
                make_float4(lo[0] * rl, lo[1] * rl, lo[2] * rl, lo[3] * rl);
            *(float4*)(ws + p_lo * FS + c0 + 4) =
                make_float4(lo[4] * rl, lo[5] * rl, lo[6] * rl, lo[7] * rl);
            *(float4*)(ws + p_hi * FS + c0) =
                make_float4(hi[0] * rh, hi[1] * rh, hi[2] * rh, hi[3] * rh);
            *(float4*)(ws + p_hi * FS + c0 + 4) =
                make_float4(hi[4] * rh, hi[5] * rh, hi[6] * rh, hi[7] * rh);
        }
        __syncthreads();

        // --- epilogue: 16 pairs per warp, coalesced gather + red.v4 scatter ---
#pragma unroll 4
        for (int i = 0; i < 16; i++) {
            int p = wid * 16 + i;
            int ij = ijs[p];
            int ii = iis[p];
            float4 hv = *(const float4*)(h + (size_t)ij * NB + lane * 4);
            float4 wv = *(const float4*)(ws + p * FS + lane * 4);
            red4(agg + (size_t)ii * NB + lane * 4,
                 wv.x * hv.x, wv.y * hv.y, wv.z * hv.z, wv.w * hv.w);
        }
    }
}

// ---------------- launch ----------------
extern "C" void kernel_launch(void* const* d_in, const int* in_sizes, int n_in,
                              void* d_out, int out_size) {
    const float* x    = (const float*)d_in[0];
    const float* f_ij = (const float*)d_in[1];
    const float* rcut = (const float*)d_in[2];
    const float* W_in = (const float*)d_in[3];
    const float* b_in = (const float*)d_in[4];
    const float* Wf1  = (const float*)d_in[5];
    const float* bf1  = (const float*)d_in[6];
    const float* Wf2  = (const float*)d_in[7];
    const float* bf2  = (const float*)d_in[8];
    const float* Wo1  = (const float*)d_in[9];
    const float* bo1  = (const float*)d_in[10];
    const float* Wo2  = (const float*)d_in[11];
    const float* bo2  = (const float*)d_in[12];
    const int* idx_i  = (const int*)d_in[13];
    const int* idx_j  = (const int*)d_in[14];

    const int natoms = in_sizes[0] / NB;
    const int npairs = in_sizes[2];
    float* out = (float*)d_out;

    float *hp, *aggp, *tp;
    cudaGetSymbolAddress((void**)&hp, g_h);
    cudaGetSymbolAddress((void**)&aggp, g_agg);
    cudaGetSymbolAddress((void**)&tp, g_t);

    static const bool once = []() {
        cudaFuncSetAttribute(pair_kernel,
                             cudaFuncAttributeMaxDynamicSharedMemorySize, SM_BYTES);
        return true;
    }();
    (void)once;

    const int grid = 148 * 8;
    const int n4 = natoms * NB / 4;
    zero_kernel<<<(n4 + 255) / 256, 256>>>((float4*)aggp, n4);
    rowmm_kernel<false><<<grid, 128>>>(x, W_in, b_in, hp, natoms);
    dummy_kernel<<<1, 32>>>();
    pair_kernel<<<148, 256, SM_BYTES>>>(f_ij, rcut, Wf1, bf1, Wf2, bf2,
                                        idx_i, idx_j, hp, aggp, npairs);
    rowmm_kernel<true><<<grid, 128>>>(aggp, Wo1, bo1, tp, natoms);
    rowmm_kernel<false><<<grid, 128>>>(tp, Wo2, bo2, out, natoms);
}

// round 11
// speedup vs baseline: 1.2069x; 1.2069x over previous
#include <cuda_runtime.h>
#include <cstdint>

#define NB 128
#define TILE 64
#define N_ATOMS_MAX 50000

typedef unsigned long long ull;

// Scratch (device globals: allocation-free per harness rules)
__device__ float g_h[N_ATOMS_MAX * NB];
__device__ float g_agg[N_ATOMS_MAX * NB];
__device__ float g_t[N_ATOMS_MAX * NB];

// ---------------- helpers ----------------

__device__ __forceinline__ float sspf(float x) {
    float e = __expf(-fabsf(x));
    return fmaxf(x, 0.0f) + __logf(1.0f + e) - 0.69314718055994531f;
}
__device__ __forceinline__ ull pack2(float x, float y) {
    ull r; asm("mov.b64 %0, {%1, %2};" : "=l"(r) : "f"(x), "f"(y)); return r;
}
__device__ __forceinline__ ull dupf(float w) {
    ull r; asm("mov.b64 %0, {%1, %1};" : "=l"(r) : "f"(w)); return r;
}
__device__ __forceinline__ void unpack2(ull v, float& x, float& y) {
    asm("mov.b64 {%0, %1}, %2;" : "=f"(x), "=f"(y) : "l"(v));
}
__device__ __forceinline__ void fma2(ull& d, ull a, ull b) {
    asm("fma.rn.f32x2 %0, %1, %2, %3;" : "=l"(d) : "l"(a), "l"(b), "l"(d));
}
__device__ __forceinline__ void red4(float* p, float a, float b, float c, float d) {
    asm volatile("red.global.add.v4.f32 [%0], {%1,%2,%3,%4};"
                 :: "l"(p), "f"(a), "f"(b), "f"(c), "f"(d) : "memory");
}

// ---------------- zero / dummy ----------------
__global__ void zero_kernel(float4* __restrict__ p, int n4) {
    int i = blockIdx.x * blockDim.x + threadIdx.x;
    if (i < n4) p[i] = make_float4(0.f, 0.f, 0.f, 0.f);
}
__global__ void dummy_kernel() {}

// ---------------- row GEMM: Y = [ssp](X @ W + b), K=N=128, 8 rows/iter ----
template <bool DOSSP>
__global__ __launch_bounds__(128, 2) void rowmm_kernel(
    const float* __restrict__ X, const float* __restrict__ W,
    const float* __restrict__ b, float* __restrict__ Y, int nrows) {
    const int j = threadIdx.x;
    float wr[NB];
#pragma unroll
    for (int k = 0; k < NB; k++) wr[k] = W[k * NB + j];
    const float bj = b[j];
    __shared__ __align__(16) float xsh[NB * 8];
    const int ngroups = (nrows + 7) / 8;
    for (int g = blockIdx.x; g < ngroups; g += gridDim.x) {
        const int row0 = g * 8;
        __syncthreads();
#pragma unroll
        for (int r = 0; r < 8; r++) {
            int row = row0 + r;
            xsh[j * 8 + r] = (row < nrows) ? X[row * NB + j] : 0.0f;
        }
        __syncthreads();
        ull a0 = pack2(bj, bj), a1 = a0, a2 = a0, a3 = a0;
        const ulonglong2* xs2 = (const ulonglong2*)xsh;
#pragma unroll
        for (int k = 0; k < NB; k++) {
            ulonglong2 fa = xs2[2 * k];
            ulonglong2 fb = xs2[2 * k + 1];
            ull wd = dupf(wr[k]);
            fma2(a0, fa.x, wd); fma2(a1, fa.y, wd);
            fma2(a2, fb.x, wd); fma2(a3, fb.y, wd);
        }
        float yv[8];
        unpack2(a0, yv[0], yv[1]); unpack2(a1, yv[2], yv[3]);
        unpack2(a2, yv[4], yv[5]); unpack2(a3, yv[6], yv[7]);
        if (DOSSP) {
#pragma unroll
            for (int r = 0; r < 8; r++) yv[r] = sspf(yv[r]);
        }
#pragma unroll
        for (int r = 0; r < 8; r++) {
            int row = row0 + r;
            if (row < nrows) Y[row * NB + j] = yv[r];
        }
    }
}

// ---------------- pair kernel: 64-pair tile, 8p x 4c thread tile ----------------
// Stage 2 epilogue scatters DIRECTLY from registers (cols c0..c0+3 contiguous):
// no transpose through smem, no ws buffer, 3 barriers per tile.

// smem float offsets
#define SM_W2   0                    // 128*128 = 16384
#define SM_F    16384                // 20*68   = 1360
#define SM_U    17744                // 128*68  = 8704
#define SM_II   26448                // 64
#define SM_IJ   26512                // 64
#define SM_RC   26576                // 64
#define SM_FLOATS 26640
#define SM_BYTES (SM_FLOATS * 4)

__global__ __launch_bounds__(256, 2) void pair_kernel(
    const float* __restrict__ f_ij, const float* __restrict__ rcut,
    const float* __restrict__ Wf1, const float* __restrict__ bf1,
    const float* __restrict__ Wf2, const float* __restrict__ bf2,
    const int* __restrict__ idx_i, const int* __restrict__ idx_j,
    const float* __restrict__ h, float* __restrict__ agg, int npairs) {
    extern __shared__ __align__(16) float sm[];
    float* W2s = sm + SM_W2;
    float* fs  = sm + SM_F;
    float* us  = sm + SM_U;
    int*   iis = (int*)(sm + SM_II);
    int*   ijs = (int*)(sm + SM_IJ);
    float* rcs = sm + SM_RC;

    const int tid  = threadIdx.x;
    const int wid  = tid >> 5;
    const int lane = tid & 31;
    const int j1   = tid & 127;     // stage-1 column
    const int ph   = tid >> 7;      // stage-1 pair half (32 pairs each)

    // persistent: Wf2 -> smem, Wf1 column -> regs
    for (int i = tid * 4; i < NB * NB; i += 1024)
        *(float4*)(W2s + i) = *(const float4*)(Wf2 + i);
    float w1r[20];
#pragma unroll
    for (int k = 0; k < 20; k++) w1r[k] = Wf1[k * NB + j1];
    const float b1 = bf1[j1];

    // stage-2 thread tile: 8 pairs (pr0..) x 4 cols (c0..)
    const int colg  = ((wid & 3) << 3) + (lane & 7);   // 0..31
    const int c0    = colg << 2;
    const int pairg = ((wid >> 2) << 2) + (lane >> 3); // 0..7
    const int pr0   = pairg << 3;
    const float4 b2v = *(const float4*)(bf2 + c0);
    const ull bd0 = dupf(b2v.x), bd1 = dupf(b2v.y), bd2 = dupf(b2v.z), bd3 = dupf(b2v.w);

    const int ntiles = (npairs + TILE - 1) / TILE;
    for (int t = blockIdx.x; t < ntiles; t += gridDim.x) {
        const int base = t * TILE;
        __syncthreads();  // prev epilogue smem reads done; W2 load done (iter 0)

        // --- f tile load + transpose to fs[k][p] ---
        if (base + TILE <= npairs) {
            for (int vi = tid; vi < TILE * 5; vi += 256) {
                float4 v = ((const float4*)f_ij)[base * 5 + vi];
                int g = vi * 4;
                int p = g / 20, k = g - p * 20;  // k in {0,4,8,12,16}: no row wrap
                fs[(k + 0) * 68 + p] = v.x;
                fs[(k + 1) * 68 + p] = v.y;
                fs[(k + 2) * 68 + p] = v.z;
                fs[(k + 3) * 68 + p] = v.w;
            }
        } else {
            for (int vi = tid; vi < TILE * 20; vi += 256) {
                int p = vi / 20, k = vi - p * 20;
                int e = base + p;
                fs[k * 68 + p] = (e < npairs) ? f_ij[e * 20 + k] : 0.0f;
            }
        }
        if (tid < TILE) {
            int e = base + tid;
            bool v = (e < npairs);
            iis[tid] = v ? idx_i[e] : 0;
            ijs[tid] = v ? idx_j[e] : 0;
            rcs[tid] = v ? rcut[e] : 0.0f;
        }
        __syncthreads();

        // --- stage 1: u[j1][ph*32..+32] = ssp(f @ Wf1[:,j1] + b1) ---
        {
            ull a[16];
            ull bi = pack2(b1, b1);
#pragma unroll
            for (int i = 0; i < 16; i++) a[i] = bi;
#pragma unroll
            for (int k = 0; k < 20; k++) {
                const ulonglong2* fp = (const ulonglong2*)(fs + k * 68 + (ph << 5));
                ull wd = dupf(w1r[k]);
#pragma unroll
                for (int q = 0; q < 8; q++) {
                    ulonglong2 fv = fp[q];
                    fma2(a[2 * q], fv.x, wd);
                    fma2(a[2 * q + 1], fv.y, wd);
                }
            }
            float v[32];
#pragma unroll
            for (int i = 0; i < 16; i++) unpack2(a[i], v[2 * i], v[2 * i + 1]);
#pragma unroll
            for (int i = 0; i < 32; i++) v[i] = sspf(v[i]);
#pragma unroll
            for (int q = 0; q < 8; q++)
                *(float4*)(us + j1 * 68 + (ph << 5) + q * 4) =
                    make_float4(v[4 * q], v[4 * q + 1], v[4 * q + 2], v[4 * q + 3]);
        }
        __syncthreads();

        // --- stage 2: acc[4 pair-pairs][4 cols] = u @ Wf2 + bf2 ---
        ull acc[16];
#pragma unroll
        for (int pp = 0; pp < 4; pp++) {
            acc[pp * 4 + 0] = bd0; acc[pp * 4 + 1] = bd1;
            acc[pp * 4 + 2] = bd2; acc[pp * 4 + 3] = bd3;
        }
        {
            const float* upb = us + pr0;
            const float* wpb = W2s + c0;
#pragma unroll 8
            for (int k = 0; k < NB; k++) {
                const ulonglong2* up = (const ulonglong2*)(upb + k * 68);
                ulonglong2 ua = up[0], ub = up[1];         // 8 pairs of u[k]
                float4 wv = *(const float4*)(wpb + (k << 7));
                ull w0 = dupf(wv.x), w1 = dupf(wv.y), w2 = dupf(wv.z), w3 = dupf(wv.w);
                fma2(acc[0],  ua.x, w0); fma2(acc[1],  ua.x, w1);
                fma2(acc[2],  ua.x, w2); fma2(acc[3],  ua.x, w3);
                fma2(acc[4],  ua.y, w0); fma2(acc[5],  ua.y, w1);
                fma2(acc[6],  ua.y, w2); fma2(acc[7],  ua.y, w3);
                fma2(acc[8],  ub.x, w0); fma2(acc[9],  ub.x, w1);
                fma2(acc[10], ub.x, w2); fma2(acc[11], ub.x, w3);
                fma2(acc[12], ub.y, w0); fma2(acc[13], ub.y, w1);
                fma2(acc[14], ub.y, w2); fma2(acc[15], ub.y, w3);
            }
        }

        // --- epilogue: direct register scatter, cols c0..c0+3 contiguous ---
        // acc[pp*4+q] = packed (pair pr0+2pp, pair pr0+2pp+1) for col c0+q
#pragma unroll
        for (int pp = 0; pp < 4; pp++) {
            int p_lo = pr0 + 2 * pp, p_hi = p_lo + 1;
            float rl = rcs[p_lo], rh = rcs[p_hi];
            int il = iis[p_lo], ihh = iis[p_hi];
            int jl = ijs[p_lo], jh = ijs[p_hi];
            float4 hl = *(const float4*)(h + (size_t)jl * NB + c0);
            float4 hh = *(const float4*)(h + (size_t)jh * NB + c0);
            float lo[4], hi[4];
#pragma unroll
            for (int q = 0; q < 4; q++) unpack2(acc[pp * 4 + q], lo[q], hi[q]);
            red4(agg + (size_t)il * NB + c0,
                 lo[0] * rl * hl.x, lo[1] * rl * hl.y,
                 lo[2] * rl * hl.z, lo[3] * rl * hl.w);
            red4(agg + (size_t)ihh * NB + c0,
                 hi[0] * rh * hh.x, hi[1] * rh * hh.y,
                 hi[2] * rh * hh.z, hi[3] * rh * hh.w);
        }
    }
}

// ---------------- launch ----------------
extern "C" void kernel_launch(void* const* d_in, const int* in_sizes, int n_in,
                              void* d_out, int out_size) {
    const float* x    = (const float*)d_in[0];
    const float* f_ij = (const float*)d_in[1];
    const float* rcut = (const float*)d_in[2];
    const float* W_in = (const float*)d_in[3];
    const float* b_in = (const float*)d_in[4];
    const float* Wf1  = (const float*)d_in[5];
    const float* bf1  = (const float*)d_in[6];
    const float* Wf2  = (const float*)d_in[7];
    const float* bf2  = (const float*)d_in[8];
    const float* Wo1  = (const float*)d_in[9];
    const float* bo1  = (const float*)d_in[10];
    const float* Wo2  = (const float*)d_in[11];
    const float* bo2  = (const float*)d_in[12];
    const int* idx_i  = (const int*)d_in[13];
    const int* idx_j  = (const int*)d_in[14];

    const int natoms = in_sizes[0] / NB;
    const int npairs = in_sizes[2];
    float* out = (float*)d_out;

    float *hp, *aggp, *tp;
    cudaGetSymbolAddress((void**)&hp, g_h);
    cudaGetSymbolAddress((void**)&aggp, g_agg);
    cudaGetSymbolAddress((void**)&tp, g_t);

    static const bool once = []() {
        cudaFuncSetAttribute(pair_kernel,
                             cudaFuncAttributeMaxDynamicSharedMemorySize, SM_BYTES);
        return true;
    }();
    (void)once;

    const int grid = 148 * 8;
    const int n4 = natoms * NB / 4;
    zero_kernel<<<(n4 + 255) / 256, 256>>>((float4*)aggp, n4);
    rowmm_kernel<false><<<grid, 128>>>(x, W_in, b_in, hp, natoms);
    dummy_kernel<<<1, 32>>>();
    pair_kernel<<<148 * 2, 256, SM_BYTES>>>(f_ij, rcut, Wf1, bf1, Wf2, bf2,
                                            idx_i, idx_j, hp, aggp, npairs);
    rowmm_kernel<true><<<grid, 128>>>(aggp, Wo1, bo1, tp, natoms);
    rowmm_kernel<false><<<grid, 128>>>(tp, Wo2, bo2, out, natoms);
}